// round 5
// baseline (speedup 1.0000x reference)
#include <cuda_runtime.h>
#include <cstddef>

#define NPIX      49152
#define NBATCH    16
#define NBUCKETS  8
#define C_IN      16
#define OUT_DIM   64
#define PROJ_IN   136      // 8*16 + 8
#define PROJ_MID  128
#define ROWS      (NBATCH * NPIX)          // 786432
#define LN_EPS    1e-5f

#define TILE_M    128
#define MLP_THREADS 512

// Scratch: per-cell channel sums + counts. Zero-initialized at module load;
// k_mlp re-zeros the region it consumes so every call sees a clean buffer.
__device__ float g_sums[(size_t)ROWS * NBUCKETS * C_IN];   // ~402 MB
__device__ float g_counts[(size_t)ROWS * NBUCKETS];        // ~25 MB

// ---------------------------------------------------------------------------
// packed f32x2 helpers (sm_10x): fma.rn.f32x2 doubles FFMA throughput
// ---------------------------------------------------------------------------
__device__ __forceinline__ unsigned long long pk2(float lo, float hi) {
    unsigned long long r;
    asm("mov.b64 %0, {%1, %2};" : "=l"(r) : "f"(lo), "f"(hi));
    return r;
}
__device__ __forceinline__ void upk2(unsigned long long v, float& lo, float& hi) {
    asm("mov.b64 {%0, %1}, %2;" : "=f"(lo), "=f"(hi) : "l"(v));
}
__device__ __forceinline__ void ffma2(unsigned long long& d,
                                      unsigned long long a,
                                      unsigned long long b) {
    asm("fma.rn.f32x2 %0, %1, %2, %3;" : "=l"(d) : "l"(a), "l"(b), "l"(d));
}

// ---------------------------------------------------------------------------
// Phase 1: scatter-add. Grid-stride; vector red.v4 for the 16 channels
// (4 ops instead of 16) + one scalar red for the count.
// ---------------------------------------------------------------------------
__global__ void __launch_bounds__(256) k_scatter(
    const float4* __restrict__ x4,
    const int*    __restrict__ bidx,
    const int*    __restrict__ pix,
    const int*    __restrict__ bkt,
    int n)
{
    for (int i = blockIdx.x * 256 + threadIdx.x; i < n; i += gridDim.x * 256) {
        size_t flat = ((size_t)bidx[i] * NPIX + (size_t)pix[i]) * NBUCKETS + (size_t)bkt[i];
        float* dst = g_sums + flat * C_IN;

        float4 v0 = x4[(size_t)i * 4 + 0];
        float4 v1 = x4[(size_t)i * 4 + 1];
        float4 v2 = x4[(size_t)i * 4 + 2];
        float4 v3 = x4[(size_t)i * 4 + 3];

        asm volatile("red.global.add.v4.f32 [%0], {%1,%2,%3,%4};"
                     :: "l"(dst +  0), "f"(v0.x), "f"(v0.y), "f"(v0.z), "f"(v0.w) : "memory");
        asm volatile("red.global.add.v4.f32 [%0], {%1,%2,%3,%4};"
                     :: "l"(dst +  4), "f"(v1.x), "f"(v1.y), "f"(v1.z), "f"(v1.w) : "memory");
        asm volatile("red.global.add.v4.f32 [%0], {%1,%2,%3,%4};"
                     :: "l"(dst +  8), "f"(v2.x), "f"(v2.y), "f"(v2.z), "f"(v2.w) : "memory");
        asm volatile("red.global.add.v4.f32 [%0], {%1,%2,%3,%4};"
                     :: "l"(dst + 12), "f"(v3.x), "f"(v3.y), "f"(v3.z), "f"(v3.w) : "memory");

        atomicAdd(g_counts + flat, 1.0f);   // result unused -> REDG
    }
}

// ---------------------------------------------------------------------------
// Phase 2: fused  mean -> concat(present) -> GEMM1 -> LN -> SiLU -> GEMM2.
// One block = 128 rows. 512 threads, each owns a 4-row x 8-col tile of h
// (GEMM1) and a 4x4 tile of out (GEMM2). Weights cached in dynamic smem.
// Also zeroes the g_sums/g_counts region it consumed (for the next replay).
// ---------------------------------------------------------------------------
// smem layout (floats):
//   sW1  : 136*128 = 17408
//   sAH  : 17408   (A tile [128][136] during GEMM1, reused as H [128][128])
//   sW2  : 128*64  = 8192
//   sCnt : 128*8   = 1024
//   sB1  : 128 ; sG : 128 ; sBt : 128 ; sB2 : 64
//   sRed : 128*16 float2 = 4096 ; sStat : 128 float2 = 256
// total = 48832 floats = 195328 bytes
#define SMEM_FLOATS 48832
#define SMEM_BYTES  (SMEM_FLOATS * 4)

__global__ void __launch_bounds__(MLP_THREADS, 1) k_mlp(
    const float* __restrict__ W1, const float* __restrict__ b1,
    const float* __restrict__ gamma, const float* __restrict__ beta,
    const float* __restrict__ W2, const float* __restrict__ b2,
    float* __restrict__ out)
{
    extern __shared__ float sm[];
    float*  sW1  = sm;
    float*  sAH  = sW1 + PROJ_IN * PROJ_MID;
    float*  sW2  = sAH + TILE_M * PROJ_IN;
    float*  sCnt = sW2 + PROJ_MID * OUT_DIM;
    float*  sB1  = sCnt + TILE_M * NBUCKETS;
    float*  sG   = sB1 + 128;
    float*  sBt  = sG + 128;
    float*  sB2  = sBt + 128;
    float2* sRed = (float2*)(sB2 + 64);
    float2* sStat = sRed + TILE_M * 16;

    const int t  = threadIdx.x;
    const int tx = t & 15;       // 16 col groups
    const int ty = t >> 4;       // 32 row groups of 4 rows
    const int r0 = ty * 4;
    const int rowStart = blockIdx.x * TILE_M;

    // ---- stage weights ----
    {
        const float4* s = (const float4*)W1;
        float4* d = (float4*)sW1;
        #pragma unroll
        for (int i = t; i < PROJ_IN * PROJ_MID / 4; i += MLP_THREADS) d[i] = s[i];
        const float4* s2 = (const float4*)W2;
        float4* d2 = (float4*)sW2;
        #pragma unroll
        for (int i = t; i < PROJ_MID * OUT_DIM / 4; i += MLP_THREADS) d2[i] = s2[i];
        if (t < 128) { sB1[t] = b1[t]; sG[t] = gamma[t]; sBt[t] = beta[t]; }
        else if (t < 192) sB2[t - 128] = b2[t - 128];
    }

    // ---- counts -> sCnt + presence flags; zero g_counts region ----
    {
        float* gc = g_counts + (size_t)rowStart * NBUCKETS;
        for (int i = t; i < TILE_M * NBUCKETS; i += MLP_THREADS) {
            float c = gc[i];
            gc[i] = 0.0f;
            sCnt[i] = c;
            int row = i >> 3, kb = i & 7;
            sAH[row * PROJ_IN + PROJ_MID + kb] = (c > 0.0f) ? 1.0f : 0.0f;
        }
    }
    __syncthreads();

    // ---- sums -> means into sA; zero g_sums region ----
    {
        float4* gs = (float4*)(g_sums + (size_t)rowStart * (NBUCKETS * C_IN));
        for (int q = t; q < TILE_M * 32; q += MLP_THREADS) {   // 32 float4 per row
            float4 v = gs[q];
            gs[q] = make_float4(0.f, 0.f, 0.f, 0.f);
            int row = q >> 5, f = q & 31, kb = f >> 2;
            float inv = 1.0f / fmaxf(sCnt[row * 8 + kb], 1.0f);
            v.x *= inv; v.y *= inv; v.z *= inv; v.w *= inv;
            *(float4*)&sAH[row * PROJ_IN + f * 4] = v;
        }
    }
    __syncthreads();

    // ---- GEMM1: h[128][128] = A[128][136] * W1[136][128], f32x2 packed ----
    unsigned long long acc[4][4];
    #pragma unroll
    for (int i = 0; i < 4; i++)
        #pragma unroll
        for (int j = 0; j < 4; j++) acc[i][j] = 0ull;

    {
        const float* Ab = sAH + r0 * PROJ_IN;
        const float* Wb = sW1 + tx * 8;
        #pragma unroll 2
        for (int k = 0; k < PROJ_IN; ++k) {
            float a0 = Ab[k];
            float a1 = Ab[PROJ_IN + k];
            float a2 = Ab[2 * PROJ_IN + k];
            float a3 = Ab[3 * PROJ_IN + k];
            unsigned long long A0 = pk2(a0, a0);
            unsigned long long A1 = pk2(a1, a1);
            unsigned long long A2 = pk2(a2, a2);
            unsigned long long A3 = pk2(a3, a3);
            ulonglong2 wlo = *(const ulonglong2*)(Wb + (size_t)k * PROJ_MID);
            ulonglong2 whi = *(const ulonglong2*)(Wb + (size_t)k * PROJ_MID + 4);
            ffma2(acc[0][0], A0, wlo.x); ffma2(acc[0][1], A0, wlo.y);
            ffma2(acc[0][2], A0, whi.x); ffma2(acc[0][3], A0, whi.y);
            ffma2(acc[1][0], A1, wlo.x); ffma2(acc[1][1], A1, wlo.y);
            ffma2(acc[1][2], A1, whi.x); ffma2(acc[1][3], A1, whi.y);
            ffma2(acc[2][0], A2, wlo.x); ffma2(acc[2][1], A2, wlo.y);
            ffma2(acc[2][2], A2, whi.x); ffma2(acc[2][3], A2, whi.y);
            ffma2(acc[3][0], A3, wlo.x); ffma2(acc[3][1], A3, wlo.y);
            ffma2(acc[3][2], A3, whi.x); ffma2(acc[3][3], A3, whi.y);
        }
    }

    // ---- +b1, per-row partial stats ----
    float h[4][8];
    #pragma unroll
    for (int i = 0; i < 4; i++) {
        float s = 0.f, s2 = 0.f;
        #pragma unroll
        for (int j = 0; j < 4; j++) {
            float lo, hi;
            upk2(acc[i][j], lo, hi);
            int c = tx * 8 + 2 * j;
            lo += sB1[c]; hi += sB1[c + 1];
            h[i][2 * j] = lo; h[i][2 * j + 1] = hi;
            s += lo + hi;
            s2 += lo * lo + hi * hi;
        }
        sRed[(r0 + i) * 16 + tx] = make_float2(s, s2);
    }
    __syncthreads();   // also guarantees all GEMM1 A-reads done before sH overwrite

    if (t < TILE_M) {
        float s = 0.f, s2 = 0.f;
        #pragma unroll
        for (int j = 0; j < 16; j++) { float2 v = sRed[t * 16 + j]; s += v.x; s2 += v.y; }
        float mu  = s * (1.0f / 128.0f);
        float var = s2 * (1.0f / 128.0f) - mu * mu;
        sStat[t] = make_float2(mu, rsqrtf(var + LN_EPS));
    }
    __syncthreads();

    // ---- LN + SiLU -> sH (reuses sAH, stride 128) ----
    float* sH = sAH;
    #pragma unroll
    for (int i = 0; i < 4; i++) {
        float2 st = sStat[r0 + i];
        float v[8];
        #pragma unroll
        for (int j = 0; j < 8; j++) {
            int c = tx * 8 + j;
            float z = (h[i][j] - st.x) * st.y * sG[c] + sBt[c];
            float sg = 1.0f / (1.0f + __expf(-z));
            v[j] = z * sg;
        }
        float4* dst = (float4*)&sH[(r0 + i) * PROJ_MID + tx * 8];
        dst[0] = make_float4(v[0], v[1], v[2], v[3]);
        dst[1] = make_float4(v[4], v[5], v[6], v[7]);
    }
    __syncthreads();

    // ---- GEMM2: out[128][64] = H[128][128] * W2[128][64], f32x2 packed ----
    unsigned long long oc[4][2];
    #pragma unroll
    for (int i = 0; i < 4; i++) { oc[i][0] = 0ull; oc[i][1] = 0ull; }
    {
        const float* Hb = sH + r0 * PROJ_MID;
        const float* Wb = sW2 + tx * 4;
        #pragma unroll 4
        for (int k = 0; k < PROJ_MID; ++k) {
            float a0 = Hb[k];
            float a1 = Hb[PROJ_MID + k];
            float a2 = Hb[2 * PROJ_MID + k];
            float a3 = Hb[3 * PROJ_MID + k];
            ulonglong2 w = *(const ulonglong2*)(Wb + (size_t)k * OUT_DIM);
            unsigned long long A0 = pk2(a0, a0);
            unsigned long long A1 = pk2(a1, a1);
            unsigned long long A2 = pk2(a2, a2);
            unsigned long long A3 = pk2(a3, a3);
            ffma2(oc[0][0], A0, w.x); ffma2(oc[0][1], A0, w.y);
            ffma2(oc[1][0], A1, w.x); ffma2(oc[1][1], A1, w.y);
            ffma2(oc[2][0], A2, w.x); ffma2(oc[2][1], A2, w.y);
            ffma2(oc[3][0], A3, w.x); ffma2(oc[3][1], A3, w.y);
        }
    }
    #pragma unroll
    for (int i = 0; i < 4; i++) {
        float x0, x1, x2, x3;
        upk2(oc[i][0], x0, x1);
        upk2(oc[i][1], x2, x3);
        int c = tx * 4;
        x0 += sB2[c]; x1 += sB2[c + 1]; x2 += sB2[c + 2]; x3 += sB2[c + 3];
        size_t row = (size_t)(rowStart + r0 + i);
        *(float4*)&out[row * OUT_DIM + c] = make_float4(x0, x1, x2, x3);
    }
}

// ---------------------------------------------------------------------------
extern "C" void kernel_launch(void* const* d_in, const int* in_sizes, int n_in,
                              void* d_out, int out_size)
{
    const float* x    = (const float*)d_in[0];
    const int*   bidx = (const int*)d_in[1];
    const int*   pix  = (const int*)d_in[2];
    const int*   bkt  = (const int*)d_in[3];

    // Locate W1 by size (robust to whether scalar inputs are materialized);
    // require the following tensor to look like b1 (size PROJ_MID).
    int iW1 = -1;
    for (int i = 4; i + 5 < n_in; ++i)
        if (in_sizes[i] == PROJ_IN * PROJ_MID && in_sizes[i + 1] == PROJ_MID) { iW1 = i; break; }
    if (iW1 < 0) {
        for (int i = 4; i < n_in; ++i)
            if (in_sizes[i] == PROJ_IN * PROJ_MID) { iW1 = i; break; }
    }
    const float* W1    = (const float*)d_in[iW1];
    const float* b1    = (const float*)d_in[iW1 + 1];
    const float* gamma = (const float*)d_in[iW1 + 2];
    const float* beta  = (const float*)d_in[iW1 + 3];
    const float* W2    = (const float*)d_in[iW1 + 4];
    const float* b2    = (const float*)d_in[iW1 + 5];
    float* out = (float*)d_out;

    int n = in_sizes[1];                       // number of points
    if (n <= 0) n = in_sizes[0] / C_IN;        // fallback

    cudaFuncSetAttribute(k_mlp, cudaFuncAttributeMaxDynamicSharedMemorySize, SMEM_BYTES);

    int nblk = (n + 255) / 256;
    if (nblk > 65535) nblk = 65535;            // grid-stride covers the rest
    k_scatter<<<nblk, 256>>>((const float4*)x, bidx, pix, bkt, n);
    k_mlp<<<ROWS / TILE_M, MLP_THREADS, SMEM_BYTES>>>(W1, b1, gamma, beta, W2, b2, out);
}